// round 2
// baseline (speedup 1.0000x reference)
#include <cuda_runtime.h>
#include <cuda_bf16.h>

// LIF neuron scan:
//   u[t] = tau * u[t-1] + x[t];  o[t] = (u[t] > 1);  u[t] *= (1 - o[t])
// x: [B, T, N] fp32, out: [B, T, N] fp32.  B=32, T=32, N=65536.
// Each thread owns 4 consecutive n-lanes (float4) of one batch row and walks T.
// All loads/stores coalesced; fully unrolled so ptxas can batch loads (MLP).
// Output is never re-read -> streaming store (__stwt) to keep L2 for the read stream.

#define T_STEPS 32
#define B_BATCH 32

__global__ __launch_bounds__(256) void lif_scan_kernel(
    const float4* __restrict__ x,
    const float*  __restrict__ tau_p,
    float4*       __restrict__ out,
    int nv,          // N/4 (float4 lanes per (b,t) row)
    int total)       // B * nv
{
    int i = blockIdx.x * blockDim.x + threadIdx.x;
    if (i >= total) return;

    // clamp learned decay to [0,1]
    float tau = __ldg(tau_p);
    tau = fminf(fmaxf(tau, 0.0f), 1.0f);

    int b = i / nv;          // nv is a power of two (16384); compiler -> shift
    int j = i - b * nv;

    size_t base = (size_t)b * T_STEPS * nv + j;
    const float4* xb = x   + base;
    float4*       ob = out + base;

    float ux = 0.0f, uy = 0.0f, uz = 0.0f, uw = 0.0f;

#pragma unroll
    for (int t = 0; t < T_STEPS; t++) {
        float4 xi = __ldg(&xb[(size_t)t * nv]);

        ux = fmaf(tau, ux, xi.x);
        uy = fmaf(tau, uy, xi.y);
        uz = fmaf(tau, uz, xi.z);
        uw = fmaf(tau, uw, xi.w);

        float4 o;
        o.x = (ux > 1.0f) ? 1.0f : 0.0f;
        o.y = (uy > 1.0f) ? 1.0f : 0.0f;
        o.z = (uz > 1.0f) ? 1.0f : 0.0f;
        o.w = (uw > 1.0f) ? 1.0f : 0.0f;

        // multiplicative soft reset: u = u * (1 - o)  ==  (u>1 ? 0 : u)
        ux = (ux > 1.0f) ? 0.0f : ux;
        uy = (uy > 1.0f) ? 0.0f : uy;
        uz = (uz > 1.0f) ? 0.0f : uz;
        uw = (uw > 1.0f) ? 0.0f : uw;

        // streaming store: output is dead after this kernel, don't cache it
        __stwt(&ob[(size_t)t * nv], o);
    }
}

extern "C" void kernel_launch(void* const* d_in, const int* in_sizes, int n_in,
                              void* d_out, int out_size)
{
    const float* x   = (const float*)d_in[0];   // [B, T, N] fp32
    const float* tau = (const float*)d_in[1];   // [1] fp32

    // Shape: B=32, T=32, N=in_sizes[0]/(B*T). Derive nv from the actual size.
    int total_elems = in_sizes[0];                       // B*T*N
    int N  = total_elems / (B_BATCH * T_STEPS);
    int nv = N / 4;                                      // float4 per (b,t) row
    int total_threads = B_BATCH * nv;                    // B * nv

    int block = 256;
    int grid  = (total_threads + block - 1) / block;

    lif_scan_kernel<<<grid, block>>>(
        (const float4*)x, tau, (float4*)d_out, nv, total_threads);
}

// round 3
// speedup vs baseline: 1.0218x; 1.0218x over previous
#include <cuda_runtime.h>
#include <cuda_bf16.h>

// LIF neuron scan:
//   u[t] = tau * u[t-1] + x[t];  o[t] = (u[t] > 1);  u[t] *= (1 - o[t])
// x: [B, T, N] fp32, out: [B, T, N] fp32.  B=32, T=32, N=65536.
//
// R3: explicit software-prefetch pipeline (depth 4) so each thread keeps 4
// independent LDG.128 in flight (addresses along T are independent of the
// scan value), doubling SM-level MLP vs the ptxas-scheduled version (regs=34
// showed it kept almost nothing in flight). Streaming hints on both sides:
// input and output are each touched exactly once (__ldcs / __stcs).

#define T_STEPS 32
#define B_BATCH 32
#define PF 4            // prefetch depth (float4 regs: 16)

__global__ __launch_bounds__(128) void lif_scan_kernel(
    const float4* __restrict__ x,
    const float*  __restrict__ tau_p,
    float4*       __restrict__ out,
    int nv,          // N/4 (float4 lanes per (b,t) row)
    int total)       // B * nv
{
    int i = blockIdx.x * blockDim.x + threadIdx.x;
    if (i >= total) return;

    // clamp learned decay to [0,1]
    float tau = __ldg(tau_p);
    tau = fminf(fmaxf(tau, 0.0f), 1.0f);

    int b = i / nv;          // nv is a power of two; compiler -> shift
    int j = i - b * nv;

    size_t base = (size_t)b * T_STEPS * nv + j;
    const float4* xb = x   + base;
    float4*       ob = out + base;

    // prime the pipeline: PF independent loads in flight
    float4 buf[PF];
#pragma unroll
    for (int t = 0; t < PF; t++)
        buf[t] = __ldcs(&xb[(size_t)t * nv]);

    float ux = 0.0f, uy = 0.0f, uz = 0.0f, uw = 0.0f;

#pragma unroll
    for (int t = 0; t < T_STEPS; t++) {
        float4 xi = buf[t % PF];
        // refill the slot we just consumed (keeps PF loads outstanding)
        if (t + PF < T_STEPS)
            buf[t % PF] = __ldcs(&xb[(size_t)(t + PF) * nv]);

        ux = fmaf(tau, ux, xi.x);
        uy = fmaf(tau, uy, xi.y);
        uz = fmaf(tau, uz, xi.z);
        uw = fmaf(tau, uw, xi.w);

        float4 o;
        o.x = (ux > 1.0f) ? 1.0f : 0.0f;
        o.y = (uy > 1.0f) ? 1.0f : 0.0f;
        o.z = (uz > 1.0f) ? 1.0f : 0.0f;
        o.w = (uw > 1.0f) ? 1.0f : 0.0f;

        // multiplicative soft reset: u = u * (1 - o)  ==  (u>1 ? 0 : u)
        ux = (ux > 1.0f) ? 0.0f : ux;
        uy = (uy > 1.0f) ? 0.0f : uy;
        uz = (uz > 1.0f) ? 0.0f : uz;
        uw = (uw > 1.0f) ? 0.0f : uw;

        // streaming store: output is dead after this kernel
        __stcs(&ob[(size_t)t * nv], o);
    }
}

extern "C" void kernel_launch(void* const* d_in, const int* in_sizes, int n_in,
                              void* d_out, int out_size)
{
    const float* x   = (const float*)d_in[0];   // [B, T, N] fp32
    const float* tau = (const float*)d_in[1];   // [1] fp32

    int total_elems = in_sizes[0];                       // B*T*N
    int N  = total_elems / (B_BATCH * T_STEPS);
    int nv = N / 4;                                      // float4 per (b,t) row
    int total_threads = B_BATCH * nv;                    // B * nv

    int block = 128;
    int grid  = (total_threads + block - 1) / block;

    lif_scan_kernel<<<grid, block>>>(
        (const float4*)x, tau, (float4*)d_out, nv, total_threads);
}

// round 4
// speedup vs baseline: 1.0236x; 1.0018x over previous
#include <cuda_runtime.h>
#include <cuda_bf16.h>

// LIF neuron scan:
//   u[t] = tau * u[t-1] + x[t];  o[t] = (u[t] > 1);  u[t] *= (1 - o[t])
// x: [B, T, N] fp32, out: [B, T, N] fp32.  B=32, T=32, N=65536.
//
// R4: batch reads/writes in chunks of 8 T-steps. Each thread issues 8
// independent LDG.128 (4KB/warp read burst), runs the scan for those 8 steps
// into a register output buffer, then issues 8 STG.128 (4KB/warp write
// burst). Coarser R/W interleave granularity -> fewer DRAM bus turnarounds,
// and guaranteed front-batched loads (MLP_p1=8) in SASS.

#define T_STEPS 32
#define B_BATCH 32
#define CHUNK   8       // T-steps per load/store batch (4 chunks total)

__global__ __launch_bounds__(128) void lif_scan_kernel(
    const float4* __restrict__ x,
    const float*  __restrict__ tau_p,
    float4*       __restrict__ out,
    int nv,          // N/4 (float4 lanes per (b,t) row)
    int total)       // B * nv
{
    int i = blockIdx.x * blockDim.x + threadIdx.x;
    if (i >= total) return;

    // clamp learned decay to [0,1]
    float tau = __ldg(tau_p);
    tau = fminf(fmaxf(tau, 0.0f), 1.0f);

    int b = i / nv;          // nv is a power of two; compiler -> shift
    int j = i - b * nv;

    size_t base = (size_t)b * T_STEPS * nv + j;
    const float4* xb = x   + base;
    float4*       ob = out + base;

    float ux = 0.0f, uy = 0.0f, uz = 0.0f, uw = 0.0f;

#pragma unroll
    for (int c = 0; c < T_STEPS / CHUNK; c++) {
        const size_t coff = (size_t)c * CHUNK * nv;

        // ---- read burst: 8 independent 16B loads ----
        float4 buf[CHUNK];
#pragma unroll
        for (int t = 0; t < CHUNK; t++)
            buf[t] = __ldcs(&xb[coff + (size_t)t * nv]);

        // ---- compute: sequential scan over the chunk (in registers) ----
#pragma unroll
        for (int t = 0; t < CHUNK; t++) {
            float4 xi = buf[t];

            ux = fmaf(tau, ux, xi.x);
            uy = fmaf(tau, uy, xi.y);
            uz = fmaf(tau, uz, xi.z);
            uw = fmaf(tau, uw, xi.w);

            float4 o;
            o.x = (ux > 1.0f) ? 1.0f : 0.0f;
            o.y = (uy > 1.0f) ? 1.0f : 0.0f;
            o.z = (uz > 1.0f) ? 1.0f : 0.0f;
            o.w = (uw > 1.0f) ? 1.0f : 0.0f;

            // multiplicative soft reset: u = (u>1 ? 0 : u)
            ux = (ux > 1.0f) ? 0.0f : ux;
            uy = (uy > 1.0f) ? 0.0f : uy;
            uz = (uz > 1.0f) ? 0.0f : uz;
            uw = (uw > 1.0f) ? 0.0f : uw;

            buf[t] = o;   // reuse the input buffer as the output buffer
        }

        // ---- write burst: 8 back-to-back 16B streaming stores ----
#pragma unroll
        for (int t = 0; t < CHUNK; t++)
            __stcs(&ob[coff + (size_t)t * nv], buf[t]);
    }
}

extern "C" void kernel_launch(void* const* d_in, const int* in_sizes, int n_in,
                              void* d_out, int out_size)
{
    const float* x   = (const float*)d_in[0];   // [B, T, N] fp32
    const float* tau = (const float*)d_in[1];   // [1] fp32

    int total_elems = in_sizes[0];                       // B*T*N
    int N  = total_elems / (B_BATCH * T_STEPS);
    int nv = N / 4;                                      // float4 per (b,t) row
    int total_threads = B_BATCH * nv;                    // B * nv

    int block = 128;
    int grid  = (total_threads + block - 1) / block;

    lif_scan_kernel<<<grid, block>>>(
        (const float4*)x, tau, (float4*)d_out, nv, total_threads);
}

// round 6
// speedup vs baseline: 1.0527x; 1.0284x over previous
#include <cuda_runtime.h>
#include <cuda_bf16.h>

// LIF neuron scan:
//   u[t] = tau * u[t-1] + x[t];  o[t] = (u[t] > 1);  u[t] *= (1 - o[t])
// x: [B, T, N] fp32, out: [B, T, N] fp32.  B=32, T=32, N=65536.
//
// R6 (= R5 resubmit after infra failure): CHUNK=16 burst batching. Each
// thread issues 16 independent LDG.128 back-to-back (8KB/warp read run),
// scans 16 steps in registers, then 16 back-to-back STG.128 (8KB/warp write
// run). Whole kernel = 2 read runs + 2 write runs per thread -> longest
// same-direction DRAM scheduler runs. Occupancy drops to ~31%; R2-R4 showed
// occupancy (66/56/50%) has no effect on this kernel.

#define T_STEPS 32
#define B_BATCH 32
#define CHUNK   16      // T-steps per load/store batch (2 chunks total)

__global__ __launch_bounds__(128) void lif_scan_kernel(
    const float4* __restrict__ x,
    const float*  __restrict__ tau_p,
    float4*       __restrict__ out,
    int nv,          // N/4 (float4 lanes per (b,t) row)
    int total)       // B * nv
{
    int i = blockIdx.x * blockDim.x + threadIdx.x;
    if (i >= total) return;

    // clamp learned decay to [0,1]
    float tau = __ldg(tau_p);
    tau = fminf(fmaxf(tau, 0.0f), 1.0f);

    int b = i / nv;          // nv is a power of two; compiler -> shift
    int j = i - b * nv;

    size_t base = (size_t)b * T_STEPS * nv + j;
    const float4* xb = x   + base;
    float4*       ob = out + base;

    float ux = 0.0f, uy = 0.0f, uz = 0.0f, uw = 0.0f;

#pragma unroll
    for (int c = 0; c < T_STEPS / CHUNK; c++) {
        const size_t coff = (size_t)c * CHUNK * nv;

        // ---- read run: 16 independent 16B loads, back-to-back ----
        float4 buf[CHUNK];
#pragma unroll
        for (int t = 0; t < CHUNK; t++)
            buf[t] = __ldcs(&xb[coff + (size_t)t * nv]);

        // ---- compute: sequential scan over the chunk (registers only) ----
#pragma unroll
        for (int t = 0; t < CHUNK; t++) {
            float4 xi = buf[t];

            ux = fmaf(tau, ux, xi.x);
            uy = fmaf(tau, uy, xi.y);
            uz = fmaf(tau, uz, xi.z);
            uw = fmaf(tau, uw, xi.w);

            float4 o;
            o.x = (ux > 1.0f) ? 1.0f : 0.0f;
            o.y = (uy > 1.0f) ? 1.0f : 0.0f;
            o.z = (uz > 1.0f) ? 1.0f : 0.0f;
            o.w = (uw > 1.0f) ? 1.0f : 0.0f;

            // multiplicative soft reset: u = (u>1 ? 0 : u)
            ux = (ux > 1.0f) ? 0.0f : ux;
            uy = (uy > 1.0f) ? 0.0f : uy;
            uz = (uz > 1.0f) ? 0.0f : uz;
            uw = (uw > 1.0f) ? 0.0f : uw;

            buf[t] = o;   // reuse input buffer as output buffer
        }

        // ---- write run: 16 back-to-back 16B streaming stores ----
#pragma unroll
        for (int t = 0; t < CHUNK; t++)
            __stcs(&ob[coff + (size_t)t * nv], buf[t]);
    }
}

extern "C" void kernel_launch(void* const* d_in, const int* in_sizes, int n_in,
                              void* d_out, int out_size)
{
    const float* x   = (const float*)d_in[0];   // [B, T, N] fp32
    const float* tau = (const float*)d_in[1];   // [1] fp32

    int total_elems = in_sizes[0];                       // B*T*N
    int N  = total_elems / (B_BATCH * T_STEPS);
    int nv = N / 4;                                      // float4 per (b,t) row
    int total_threads = B_BATCH * nv;                    // B * nv

    int block = 128;
    int grid  = (total_threads + block - 1) / block;

    lif_scan_kernel<<<grid, block>>>(
        (const float4*)x, tau, (float4*)d_out, nv, total_threads);
}